// round 1
// baseline (speedup 1.0000x reference)
#include <cuda_runtime.h>
#include <math.h>

#define B_        64
#define SEQ       784
#define SEQ_OUT   196
#define C_IN      512
#define KEY_DIM   32
#define NUM_HEADS 16
#define D_V       128
#define OUT_KV    2560
#define OUT_PROJ  2048
#define C_OUT     768
#define N_OFF     784
#define RES_OUT   14
#define SCALE_F   0.17677669529663687f  // 32^-0.5
#define BN_EPS    1e-5f

// ---- scratch (static device globals; allocation-free) ----
__device__ float g_K [(size_t)B_*NUM_HEADS*SEQ*KEY_DIM];      //  98 MB
__device__ float g_V [(size_t)B_*NUM_HEADS*SEQ*D_V];          // 392 MB
__device__ float g_Q [(size_t)B_*NUM_HEADS*SEQ_OUT*KEY_DIM];  //  25 MB
__device__ float g_HS[(size_t)B_*SEQ_OUT*OUT_PROJ];           //  98 MB

// ============================================================
// Tiled fp32 GEMM  C[M,N] = A[M,K] @ W[N,K]^T  with fused BN epilogue.
// BM=BN=128, BK=8, 256 threads, 8x8 microtile.
// MODE 0: A=x, split write to g_K / g_V
// MODE 1: A=x with strided-row gather (q path), write g_Q
// MODE 2: A=g_HS, write d_out
// ============================================================
template<int MODE>
__global__ void __launch_bounds__(256, 2)
gemm_bn_kernel(const float* __restrict__ A, const float* __restrict__ W,
               const float* __restrict__ bng, const float* __restrict__ bnb,
               const float* __restrict__ bnm, const float* __restrict__ bnv,
               float* __restrict__ out, int M, int N, int K)
{
    __shared__ float As[8][128];
    __shared__ float Bs[8][128];

    const int bm = blockIdx.x * 128;
    const int bn = blockIdx.y * 128;
    const int t  = threadIdx.x;

    const int la_m = t >> 1;          // 0..127
    const int la_k = (t & 1) * 4;     // 0 or 4

    const float* a_src;
    if (MODE == 1) {
        int row = bm + la_m;
        int b = row / SEQ_OUT, sq = row % SEQ_OUT;
        int r = sq / RES_OUT, c = sq % RES_OUT;
        a_src = A + ((size_t)b * SEQ + (2*r*28 + 2*c)) * C_IN;
    } else if (MODE == 2) {
        a_src = g_HS + (size_t)(bm + la_m) * K;
    } else {
        a_src = A + (size_t)(bm + la_m) * K;
    }
    const float* b_src = W + (size_t)(bn + la_m) * K;

    float acc[8][8];
    #pragma unroll
    for (int i = 0; i < 8; i++)
        #pragma unroll
        for (int j = 0; j < 8; j++) acc[i][j] = 0.f;

    const int tm = (t >> 4) * 8;
    const int tn = (t & 15) * 8;

    for (int k0 = 0; k0 < K; k0 += 8) {
        float4 av = *(const float4*)(a_src + k0 + la_k);
        float4 bv = *(const float4*)(b_src + k0 + la_k);
        __syncthreads();
        As[la_k+0][la_m] = av.x; As[la_k+1][la_m] = av.y;
        As[la_k+2][la_m] = av.z; As[la_k+3][la_m] = av.w;
        Bs[la_k+0][la_m] = bv.x; Bs[la_k+1][la_m] = bv.y;
        Bs[la_k+2][la_m] = bv.z; Bs[la_k+3][la_m] = bv.w;
        __syncthreads();
        #pragma unroll
        for (int kk = 0; kk < 8; kk++) {
            float4 a0 = *(const float4*)&As[kk][tm];
            float4 a1 = *(const float4*)&As[kk][tm+4];
            float4 b0 = *(const float4*)&Bs[kk][tn];
            float4 b1 = *(const float4*)&Bs[kk][tn+4];
            float ar[8] = {a0.x,a0.y,a0.z,a0.w,a1.x,a1.y,a1.z,a1.w};
            float br[8] = {b0.x,b0.y,b0.z,b0.w,b1.x,b1.y,b1.z,b1.w};
            #pragma unroll
            for (int i = 0; i < 8; i++)
                #pragma unroll
                for (int j = 0; j < 8; j++) acc[i][j] += ar[i]*br[j];
        }
    }

    // fused BN epilogue
    #pragma unroll
    for (int j = 0; j < 8; j++) {
        int n = bn + tn + j;
        float sc = bng[n] * rsqrtf(bnv[n] + BN_EPS);
        float sh = bnb[n] - bnm[n] * sc;
        #pragma unroll
        for (int i = 0; i < 8; i++) {
            int m = bm + tm + i;
            float y = acc[i][j] * sc + sh;
            if (MODE == 0) {
                int b = m / SEQ, s = m % SEQ;
                int h = n / (KEY_DIM + D_V), c = n % (KEY_DIM + D_V);
                if (c < KEY_DIM)
                    g_K[(((size_t)(b*NUM_HEADS+h))*SEQ + s)*KEY_DIM + c] = y;
                else
                    g_V[(((size_t)(b*NUM_HEADS+h))*SEQ + s)*D_V + (c - KEY_DIM)] = y;
            } else if (MODE == 1) {
                int b = m / SEQ_OUT, sq = m % SEQ_OUT;
                int h = n / KEY_DIM, d = n % KEY_DIM;
                g_Q[(((size_t)(b*NUM_HEADS+h))*SEQ_OUT + sq)*KEY_DIM + d] = y;
            } else {
                out[(size_t)m * C_OUT + n] = y;
            }
        }
    }
}

// ============================================================
// Fused attention: scores + bias gather + softmax + PV + hardswish
// One CTA per (b, h, 28-query block). 224 threads, ~152 KB dynamic smem.
// ============================================================
#define QB 28
#define KC 112
#define KSTRIDE 36   // padded K-chunk row stride (bank-conflict-free)
#define ATTN_SMEM_FLOATS (QB*SEQ + QB*KEY_DIM + N_OFF + KC*D_V)
#define ATTN_SMEM_BYTES  (ATTN_SMEM_FLOATS * 4)

__global__ void __launch_bounds__(224, 1)
attn_kernel(const float* __restrict__ attn_biases,
            const int*   __restrict__ bias_idxs)
{
    extern __shared__ float sm[];
    float* sScores = sm;                       // 28*784
    float* sQ      = sScores + QB*SEQ;         // 28*32
    float* sBias   = sQ + QB*KEY_DIM;          // 784
    float* sKV     = sBias + N_OFF;            // 112*128 (reused)

    const int t    = threadIdx.x;
    const int cta  = blockIdx.x;               // b*112 + h*7 + qb
    const int qb   = cta % 7;
    const int h    = (cta / 7) % NUM_HEADS;
    const int b    = cta / (7 * NUM_HEADS);
    const int warp = t >> 5, lane = t & 31;

    const float* Kp = g_K + ((size_t)(b*NUM_HEADS+h))*SEQ*KEY_DIM;
    const float* Vp = g_V + ((size_t)(b*NUM_HEADS+h))*SEQ*D_V;
    const float* Qp = g_Q + (((size_t)(b*NUM_HEADS+h))*SEQ_OUT + qb*QB)*KEY_DIM;

    for (int i = t; i < QB*KEY_DIM; i += 224) sQ[i] = Qp[i];
    for (int i = t; i < N_OFF;      i += 224) sBias[i] = attn_biases[h*N_OFF + i];

    // ---- phase 1: scores = q.k * scale + bias ----
    for (int kc = 0; kc < SEQ; kc += KC) {
        __syncthreads();
        for (int i = t*4; i < KC*KEY_DIM; i += 224*4) {
            int row = i >> 5, d = i & 31;
            float4 v = *(const float4*)&Kp[(size_t)(kc)*KEY_DIM + i];
            *(float4*)&sKV[row*KSTRIDE + d] = v;
        }
        __syncthreads();
        for (int kk = lane; kk < KC; kk += 32) {
            float kr[KEY_DIM];
            #pragma unroll
            for (int d4 = 0; d4 < 8; d4++)
                *(float4*)&kr[d4*4] = *(const float4*)&sKV[kk*KSTRIDE + d4*4];
            #pragma unroll
            for (int qi = 0; qi < 4; qi++) {
                int q = warp*4 + qi;
                float s = 0.f;
                #pragma unroll
                for (int d4 = 0; d4 < 8; d4++) {
                    float4 q4 = *(const float4*)&sQ[q*KEY_DIM + d4*4];
                    s += q4.x*kr[d4*4] + q4.y*kr[d4*4+1] + q4.z*kr[d4*4+2] + q4.w*kr[d4*4+3];
                }
                int key = kc + kk;
                int idx = bias_idxs[(qb*QB + q)*SEQ + key];
                sScores[q*SEQ + key] = s * SCALE_F + sBias[idx];
            }
        }
    }
    __syncthreads();

    // ---- phase 2: softmax (one warp per 4 rows) ----
    for (int qi = 0; qi < 4; qi++) {
        int q = warp*4 + qi;
        float mx = -1e30f;
        for (int k = lane; k < SEQ; k += 32) mx = fmaxf(mx, sScores[q*SEQ + k]);
        #pragma unroll
        for (int o = 16; o; o >>= 1) mx = fmaxf(mx, __shfl_xor_sync(~0u, mx, o));
        float sum = 0.f;
        for (int k = lane; k < SEQ; k += 32) {
            float e = __expf(sScores[q*SEQ + k] - mx);
            sScores[q*SEQ + k] = e; sum += e;
        }
        #pragma unroll
        for (int o = 16; o; o >>= 1) sum += __shfl_xor_sync(~0u, sum, o);
        float inv = 1.f / sum;
        for (int k = lane; k < SEQ; k += 32) sScores[q*SEQ + k] *= inv;
    }

    // ---- phase 3: out = P @ V (4q x 4dv microtile per thread) ----
    float acc[4][4] = {};
    const int qg  = warp;       // 4 q rows per warp
    const int dvg = lane;       // 4 dv cols per lane
    for (int vc = 0; vc < SEQ; vc += KC) {
        __syncthreads();
        for (int i = t*4; i < KC*D_V; i += 224*4)
            *(float4*)&sKV[i] = *(const float4*)&Vp[(size_t)vc*D_V + i];
        __syncthreads();
        for (int kk = 0; kk < KC; kk++) {
            float4 v4 = *(const float4*)&sKV[kk*D_V + dvg*4];
            #pragma unroll
            for (int qi = 0; qi < 4; qi++) {
                float p = sScores[(qg*4 + qi)*SEQ + vc + kk];
                acc[qi][0] += p*v4.x; acc[qi][1] += p*v4.y;
                acc[qi][2] += p*v4.z; acc[qi][3] += p*v4.w;
            }
        }
    }

    // ---- phase 4: hardswish + store to g_HS [B, 196, 2048] ----
    #pragma unroll
    for (int qi = 0; qi < 4; qi++) {
        int q = qb*QB + qg*4 + qi;
        float4 o;
        float* po = (float*)&o;
        #pragma unroll
        for (int j = 0; j < 4; j++) {
            float x = acc[qi][j];
            float r = fminf(fmaxf(x + 3.f, 0.f), 6.f);
            po[j] = x * r * (1.f/6.f);
        }
        *(float4*)&g_HS[((size_t)b*SEQ_OUT + q)*OUT_PROJ + h*D_V + dvg*4] = o;
    }
}

// ============================================================
extern "C" void kernel_launch(void* const* d_in, const int* in_sizes, int n_in,
                              void* d_out, int out_size)
{
    const float* x      = (const float*)d_in[0];
    const float* kv_w   = (const float*)d_in[1];
    const float* kv_g   = (const float*)d_in[2];
    const float* kv_b   = (const float*)d_in[3];
    const float* kv_m   = (const float*)d_in[4];
    const float* kv_v   = (const float*)d_in[5];
    const float* q_w    = (const float*)d_in[6];
    const float* q_g    = (const float*)d_in[7];
    const float* q_b    = (const float*)d_in[8];
    const float* q_m    = (const float*)d_in[9];
    const float* q_v    = (const float*)d_in[10];
    const float* p_w    = (const float*)d_in[11];
    const float* p_g    = (const float*)d_in[12];
    const float* p_b    = (const float*)d_in[13];
    const float* p_m    = (const float*)d_in[14];
    const float* p_v    = (const float*)d_in[15];
    const float* biases = (const float*)d_in[16];
    const int*   bidx   = (const int*)d_in[17];
    float* out = (float*)d_out;

    cudaFuncSetAttribute(attn_kernel, cudaFuncAttributeMaxDynamicSharedMemorySize,
                         ATTN_SMEM_BYTES);

    // KV: [50176,512] x [2560,512]^T
    gemm_bn_kernel<0><<<dim3(50176/128, OUT_KV/128), 256>>>(
        x, kv_w, kv_g, kv_b, kv_m, kv_v, nullptr, 50176, OUT_KV, C_IN);

    // Q: [12544,512] x [512,512]^T (strided row gather)
    gemm_bn_kernel<1><<<dim3(12544/128, 512/128), 256>>>(
        x, q_w, q_g, q_b, q_m, q_v, nullptr, 12544, 512, C_IN);

    // fused attention: 64*16*7 CTAs
    attn_kernel<<<B_*NUM_HEADS*7, 224, ATTN_SMEM_BYTES>>>(biases, bidx);

    // Proj: [12544,2048] x [768,2048]^T -> d_out
    gemm_bn_kernel<2><<<dim3(12544/128, C_OUT/128), 256>>>(
        nullptr, p_w, p_g, p_b, p_m, p_v, out, 12544, C_OUT, OUT_PROJ);
}

// round 2
// speedup vs baseline: 1.3891x; 1.3891x over previous
#include <cuda_runtime.h>
#include <math.h>

#define B_        64
#define SEQ       784
#define SEQ_OUT   196
#define C_IN      512
#define KEY_DIM   32
#define NUM_HEADS 16
#define D_V       128
#define OUT_KV    2560
#define OUT_PROJ  2048
#define C_OUT     768
#define N_OFF     784
#define RES_OUT   14
#define SCALE_F   0.17677669529663687f
#define BN_EPS    1e-5f

// ---- scratch (static device globals; allocation-free) ----
__device__ float g_K [(size_t)B_*NUM_HEADS*SEQ*KEY_DIM];
__device__ float g_V [(size_t)B_*NUM_HEADS*SEQ*D_V];
__device__ float g_Q [(size_t)B_*NUM_HEADS*SEQ_OUT*KEY_DIM];
__device__ float g_HS[(size_t)B_*SEQ_OUT*OUT_PROJ];

__device__ __forceinline__ unsigned f2tf32(float f) {
    unsigned r;
    asm("cvt.rna.tf32.f32 %0, %1;" : "=r"(r) : "f"(f));
    return r;
}

__device__ __forceinline__ void mma_tf32(float* c, const unsigned* a, const unsigned* b) {
    asm volatile(
        "mma.sync.aligned.m16n8k8.row.col.f32.tf32.tf32.f32 "
        "{%0,%1,%2,%3}, {%4,%5,%6,%7}, {%8,%9}, {%0,%1,%2,%3};"
        : "+f"(c[0]), "+f"(c[1]), "+f"(c[2]), "+f"(c[3])
        : "r"(a[0]), "r"(a[1]), "r"(a[2]), "r"(a[3]), "r"(b[0]), "r"(b[1]));
}

// ============================================================
// TF32 tensor-core GEMM  C[M,N] = A[M,K] @ W[N,K]^T  + BN epilogue.
// CTA 128x128xKc16, 256 threads (8 warps, 2x4), warp tile 64x32.
// smem: k-shuffled pair layout, row stride 24 words, double buffered.
//   word pos for k in [0,16): (k&8) + 2*(k&3) + ((k&4)?1:0)
//   -> (k, k+4) adjacent => conflict-free LDS.64 fragment loads.
// MODE 0: A=x -> split g_K/g_V   MODE 1: A=x gathered rows -> g_Q
// MODE 2: A=g_HS -> d_out
// ============================================================
#define TS 24  // smem row stride in words

template<int MODE>
__global__ void __launch_bounds__(256, 2)
gemm_tc(const float* __restrict__ A, const float* __restrict__ W,
        const float* __restrict__ bng, const float* __restrict__ bnb,
        const float* __restrict__ bnm, const float* __restrict__ bnv,
        float* __restrict__ out, int M, int N, int K)
{
    __shared__ unsigned sA[2][128 * TS];
    __shared__ unsigned sB[2][128 * TS];

    const int t    = threadIdx.x;
    const int warp = t >> 5, lane = t & 31;
    const int wm   = warp >> 2, wn = warp & 3;      // 2 x 4 warp grid
    const int bm   = blockIdx.x * 128;
    const int bnn  = blockIdx.y * 128;

    // global load assignment: row lm, k-halves lk..lk+7
    const int lm = t >> 1;
    const int lk = (t & 1) * 8;

    const float* a_src;
    if (MODE == 1) {
        int row = bm + lm;
        int b = row / SEQ_OUT, sq = row - b * SEQ_OUT;
        int r = sq / RES_OUT, c2 = sq - r * RES_OUT;
        a_src = A + ((size_t)b * SEQ + (2*r*28 + 2*c2)) * C_IN;
    } else if (MODE == 2) {
        a_src = g_HS + (size_t)(bm + lm) * K;
    } else {
        a_src = A + (size_t)(bm + lm) * K;
    }
    const float* b_src = W + (size_t)(bnn + lm) * K;

    float acc[16][4];
    #pragma unroll
    for (int i = 0; i < 16; i++)
        #pragma unroll
        for (int j = 0; j < 4; j++) acc[i][j] = 0.f;

    float4 ra0, ra1, rb0, rb1;

    auto ldg = [&](int k0) {
        ra0 = *(const float4*)(a_src + k0 + lk);
        ra1 = *(const float4*)(a_src + k0 + lk + 4);
        rb0 = *(const float4*)(b_src + k0 + lk);
        rb1 = *(const float4*)(b_src + k0 + lk + 4);
    };
    auto sts = [&](int buf) {
        // float4 at local k = lk   -> base (lk&8)+0, stride 2
        // float4 at local k = lk+4 -> base (lk&8)+1, stride 2
        unsigned* pa = &sA[buf][lm * TS + (lk & 8)];
        unsigned* pb = &sB[buf][lm * TS + (lk & 8)];
        pa[0] = f2tf32(ra0.x); pa[2] = f2tf32(ra0.y); pa[4] = f2tf32(ra0.z); pa[6] = f2tf32(ra0.w);
        pa[1] = f2tf32(ra1.x); pa[3] = f2tf32(ra1.y); pa[5] = f2tf32(ra1.z); pa[7] = f2tf32(ra1.w);
        pb[0] = f2tf32(rb0.x); pb[2] = f2tf32(rb0.y); pb[4] = f2tf32(rb0.z); pb[6] = f2tf32(rb0.w);
        pb[1] = f2tf32(rb1.x); pb[3] = f2tf32(rb1.y); pb[5] = f2tf32(rb1.z); pb[7] = f2tf32(rb1.w);
    };

    ldg(0);
    sts(0);
    __syncthreads();

    const int nIter = K >> 4;
    for (int it = 0; it < nIter; ++it) {
        const int cur = it & 1;
        const bool more = (it + 1 < nIter);
        if (more) ldg((it + 1) << 4);

        #pragma unroll
        for (int g = 0; g < 2; g++) {
            unsigned af[4][4], bf[4][2];
            const int aoff = g * 8 + 2 * (lane & 3);
            #pragma unroll
            for (int mt = 0; mt < 4; mt++) {
                int r = wm * 64 + mt * 16 + (lane >> 2);
                uint2 p0 = *(const uint2*)&sA[cur][r * TS + aoff];
                uint2 p1 = *(const uint2*)&sA[cur][(r + 8) * TS + aoff];
                af[mt][0] = p0.x; af[mt][2] = p0.y;
                af[mt][1] = p1.x; af[mt][3] = p1.y;
            }
            #pragma unroll
            for (int nt = 0; nt < 4; nt++) {
                int r = wn * 32 + nt * 8 + (lane >> 2);
                uint2 p = *(const uint2*)&sB[cur][r * TS + aoff];
                bf[nt][0] = p.x; bf[nt][1] = p.y;
            }
            #pragma unroll
            for (int mt = 0; mt < 4; mt++)
                #pragma unroll
                for (int nt = 0; nt < 4; nt++)
                    mma_tf32(acc[mt * 4 + nt], af[mt], bf[nt]);
        }

        if (more) sts(cur ^ 1);
        __syncthreads();
    }

    // ---- BN epilogue + scatter ----
    #pragma unroll
    for (int nt = 0; nt < 4; nt++) {
        int c0 = bnn + wn * 32 + nt * 8 + 2 * (lane & 3);
        float sc0 = bng[c0]     * rsqrtf(bnv[c0]     + BN_EPS);
        float sh0 = bnb[c0]     - bnm[c0]     * sc0;
        float sc1 = bng[c0 + 1] * rsqrtf(bnv[c0 + 1] + BN_EPS);
        float sh1 = bnb[c0 + 1] - bnm[c0 + 1] * sc1;
        #pragma unroll
        for (int mt = 0; mt < 4; mt++) {
            #pragma unroll
            for (int half = 0; half < 2; half++) {
                int m = bm + wm * 64 + mt * 16 + (lane >> 2) + half * 8;
                float y0 = acc[mt * 4 + nt][half * 2 + 0] * sc0 + sh0;
                float y1 = acc[mt * 4 + nt][half * 2 + 1] * sc1 + sh1;
                if (MODE == 0) {
                    int b = m / SEQ, s = m - b * SEQ;
                    #pragma unroll
                    for (int e = 0; e < 2; e++) {
                        int n = c0 + e;
                        float y = e ? y1 : y0;
                        int h = n / (KEY_DIM + D_V), c = n - h * (KEY_DIM + D_V);
                        if (c < KEY_DIM)
                            g_K[(((size_t)(b*NUM_HEADS+h))*SEQ + s)*KEY_DIM + c] = y;
                        else
                            g_V[(((size_t)(b*NUM_HEADS+h))*SEQ + s)*D_V + (c - KEY_DIM)] = y;
                    }
                } else if (MODE == 1) {
                    int b = m / SEQ_OUT, sq = m - b * SEQ_OUT;
                    int h = c0 / KEY_DIM, d = c0 - h * KEY_DIM;
                    float* p = &g_Q[(((size_t)(b*NUM_HEADS+h))*SEQ_OUT + sq)*KEY_DIM + d];
                    p[0] = y0; p[1] = y1;
                } else {
                    float* p = &out[(size_t)m * C_OUT + c0];
                    p[0] = y0; p[1] = y1;
                }
            }
        }
    }
}

// ============================================================
// Fused attention: scores + bias gather + softmax + PV + hardswish
// One CTA per (b, h, 28-query block). 448 threads (14 warps), ~152 KB smem.
// ============================================================
#define QB 28
#define KC 112
#define KSTRIDE 36
#define NTHR 448
#define ATTN_SMEM_FLOATS (QB*SEQ + QB*KEY_DIM + N_OFF + KC*D_V)
#define ATTN_SMEM_BYTES  (ATTN_SMEM_FLOATS * 4)

__global__ void __launch_bounds__(NTHR, 1)
attn_kernel(const float* __restrict__ attn_biases,
            const int*   __restrict__ bias_idxs)
{
    extern __shared__ float sm[];
    float* sScores = sm;                       // 28*784
    float* sQ      = sScores + QB*SEQ;         // 28*32
    float* sBias   = sQ + QB*KEY_DIM;          // 784
    float* sKV     = sBias + N_OFF;            // 112*128 (reused)

    const int t    = threadIdx.x;
    const int cta  = blockIdx.x;
    const int qb   = cta % 7;
    const int h    = (cta / 7) % NUM_HEADS;
    const int b    = cta / (7 * NUM_HEADS);
    const int warp = t >> 5, lane = t & 31;

    const float* Kp = g_K + ((size_t)(b*NUM_HEADS+h))*SEQ*KEY_DIM;
    const float* Vp = g_V + ((size_t)(b*NUM_HEADS+h))*SEQ*D_V;
    const float* Qp = g_Q + (((size_t)(b*NUM_HEADS+h))*SEQ_OUT + qb*QB)*KEY_DIM;

    for (int i = t; i < QB*KEY_DIM; i += NTHR) sQ[i] = Qp[i];
    for (int i = t; i < N_OFF;      i += NTHR) sBias[i] = attn_biases[h*N_OFF + i];

    // ---- phase 1: scores = q.k * scale + bias (2 q rows per warp) ----
    for (int kc = 0; kc < SEQ; kc += KC) {
        __syncthreads();
        for (int i = t*4; i < KC*KEY_DIM; i += NTHR*4) {
            int row = i >> 5, d = i & 31;
            float4 v = *(const float4*)&Kp[(size_t)kc*KEY_DIM + i];
            *(float4*)&sKV[row*KSTRIDE + d] = v;
        }
        __syncthreads();
        for (int kk = lane; kk < KC; kk += 32) {
            float kr[KEY_DIM];
            #pragma unroll
            for (int d4 = 0; d4 < 8; d4++)
                *(float4*)&kr[d4*4] = *(const float4*)&sKV[kk*KSTRIDE + d4*4];
            #pragma unroll
            for (int qi = 0; qi < 2; qi++) {
                int q = warp*2 + qi;
                float s = 0.f;
                #pragma unroll
                for (int d4 = 0; d4 < 8; d4++) {
                    float4 q4 = *(const float4*)&sQ[q*KEY_DIM + d4*4];
                    s += q4.x*kr[d4*4] + q4.y*kr[d4*4+1] + q4.z*kr[d4*4+2] + q4.w*kr[d4*4+3];
                }
                int key = kc + kk;
                int idx = bias_idxs[(qb*QB + q)*SEQ + key];
                sScores[q*SEQ + key] = s * SCALE_F + sBias[idx];
            }
        }
    }
    __syncthreads();

    // ---- phase 2: softmax (2 rows per warp) ----
    #pragma unroll
    for (int qi = 0; qi < 2; qi++) {
        int q = warp*2 + qi;
        float mx = -1e30f;
        for (int k = lane; k < SEQ; k += 32) mx = fmaxf(mx, sScores[q*SEQ + k]);
        #pragma unroll
        for (int o = 16; o; o >>= 1) mx = fmaxf(mx, __shfl_xor_sync(~0u, mx, o));
        float sum = 0.f;
        for (int k = lane; k < SEQ; k += 32) {
            float e = __expf(sScores[q*SEQ + k] - mx);
            sScores[q*SEQ + k] = e; sum += e;
        }
        #pragma unroll
        for (int o = 16; o; o >>= 1) sum += __shfl_xor_sync(~0u, sum, o);
        float inv = 1.f / sum;
        for (int k = lane; k < SEQ; k += 32) sScores[q*SEQ + k] *= inv;
    }

    // ---- phase 3: out = P @ V (2q x 4dv microtile per thread) ----
    float acc[2][4] = {};
    for (int vc = 0; vc < SEQ; vc += KC) {
        __syncthreads();
        for (int i = t*4; i < KC*D_V; i += NTHR*4)
            *(float4*)&sKV[i] = *(const float4*)&Vp[(size_t)vc*D_V + i];
        __syncthreads();
        for (int kk = 0; kk < KC; kk++) {
            float4 v4 = *(const float4*)&sKV[kk*D_V + lane*4];
            #pragma unroll
            for (int qi = 0; qi < 2; qi++) {
                float p = sScores[(warp*2 + qi)*SEQ + vc + kk];
                acc[qi][0] += p*v4.x; acc[qi][1] += p*v4.y;
                acc[qi][2] += p*v4.z; acc[qi][3] += p*v4.w;
            }
        }
    }

    // ---- phase 4: hardswish + store to g_HS ----
    #pragma unroll
    for (int qi = 0; qi < 2; qi++) {
        int q = qb*QB + warp*2 + qi;
        float4 o;
        float* po = (float*)&o;
        #pragma unroll
        for (int j = 0; j < 4; j++) {
            float x = acc[qi][j];
            float r = fminf(fmaxf(x + 3.f, 0.f), 6.f);
            po[j] = x * r * (1.f/6.f);
        }
        *(float4*)&g_HS[((size_t)b*SEQ_OUT + q)*OUT_PROJ + h*D_V + lane*4] = o;
    }
}

// ============================================================
extern "C" void kernel_launch(void* const* d_in, const int* in_sizes, int n_in,
                              void* d_out, int out_size)
{
    const float* x      = (const float*)d_in[0];
    const float* kv_w   = (const float*)d_in[1];
    const float* kv_g   = (const float*)d_in[2];
    const float* kv_b   = (const float*)d_in[3];
    const float* kv_m   = (const float*)d_in[4];
    const float* kv_v   = (const float*)d_in[5];
    const float* q_w    = (const float*)d_in[6];
    const float* q_g    = (const float*)d_in[7];
    const float* q_b    = (const float*)d_in[8];
    const float* q_m    = (const float*)d_in[9];
    const float* q_v    = (const float*)d_in[10];
    const float* p_w    = (const float*)d_in[11];
    const float* p_g    = (const float*)d_in[12];
    const float* p_b    = (const float*)d_in[13];
    const float* p_m    = (const float*)d_in[14];
    const float* p_v    = (const float*)d_in[15];
    const float* biases = (const float*)d_in[16];
    const int*   bidx   = (const int*)d_in[17];
    float* out = (float*)d_out;

    cudaFuncSetAttribute(attn_kernel, cudaFuncAttributeMaxDynamicSharedMemorySize,
                         ATTN_SMEM_BYTES);

    gemm_tc<0><<<dim3(50176/128, OUT_KV/128), 256>>>(
        x, kv_w, kv_g, kv_b, kv_m, kv_v, nullptr, 50176, OUT_KV, C_IN);

    gemm_tc<1><<<dim3(12544/128, 512/128), 256>>>(
        x, q_w, q_g, q_b, q_m, q_v, nullptr, 12544, 512, C_IN);

    attn_kernel<<<B_*NUM_HEADS*7, NTHR, ATTN_SMEM_BYTES>>>(biases, bidx);

    gemm_tc<2><<<dim3(12544/128, C_OUT/128), 256>>>(
        nullptr, p_w, p_g, p_b, p_m, p_v, out, 12544, C_OUT, OUT_PROJ);
}

// round 3
// speedup vs baseline: 1.9445x; 1.3998x over previous
#include <cuda_runtime.h>
#include <math.h>

#define B_        64
#define SEQ       784
#define SEQ_OUT   196
#define C_IN      512
#define KEY_DIM   32
#define NUM_HEADS 16
#define D_V       128
#define OUT_KV    2560
#define OUT_PROJ  2048
#define C_OUT     768
#define N_OFF     784
#define RES_OUT   14
#define SCALE_F   0.17677669529663687f
#define BN_EPS    1e-5f

// ---- scratch (static device globals; allocation-free) ----
__device__ float g_K   [(size_t)B_*NUM_HEADS*SEQ*KEY_DIM];
__device__ float g_V   [(size_t)B_*NUM_HEADS*SEQ*D_V];
__device__ float g_Q   [(size_t)B_*NUM_HEADS*SEQ_OUT*KEY_DIM];
__device__ float g_HS  [(size_t)B_*SEQ_OUT*OUT_PROJ];
__device__ float g_Bias[(size_t)NUM_HEADS*SEQ_OUT*SEQ];

__device__ __forceinline__ unsigned f2tf32(float f) {
    unsigned r;
    asm("cvt.rna.tf32.f32 %0, %1;" : "=r"(r) : "f"(f));
    return r;
}

__device__ __forceinline__ void mma_tf32(float* c, const unsigned* a, const unsigned* b) {
    asm volatile(
        "mma.sync.aligned.m16n8k8.row.col.f32.tf32.tf32.f32 "
        "{%0,%1,%2,%3}, {%4,%5,%6,%7}, {%8,%9}, {%0,%1,%2,%3};"
        : "+f"(c[0]), "+f"(c[1]), "+f"(c[2]), "+f"(c[3])
        : "r"(a[0]), "r"(a[1]), "r"(a[2]), "r"(a[3]), "r"(b[0]), "r"(b[1]));
}

// ============================================================
// TF32 tensor-core GEMM (unchanged from R2)
// ============================================================
#define TS 24

template<int MODE>
__global__ void __launch_bounds__(256, 2)
gemm_tc(const float* __restrict__ A, const float* __restrict__ W,
        const float* __restrict__ bng, const float* __restrict__ bnb,
        const float* __restrict__ bnm, const float* __restrict__ bnv,
        float* __restrict__ out, int M, int N, int K)
{
    __shared__ unsigned sA[2][128 * TS];
    __shared__ unsigned sB[2][128 * TS];

    const int t    = threadIdx.x;
    const int warp = t >> 5, lane = t & 31;
    const int wm   = warp >> 2, wn = warp & 3;
    const int bm   = blockIdx.x * 128;
    const int bnn  = blockIdx.y * 128;
    const int lm   = t >> 1;
    const int lk   = (t & 1) * 8;

    const float* a_src;
    if (MODE == 1) {
        int row = bm + lm;
        int b = row / SEQ_OUT, sq = row - b * SEQ_OUT;
        int r = sq / RES_OUT, c2 = sq - r * RES_OUT;
        a_src = A + ((size_t)b * SEQ + (2*r*28 + 2*c2)) * C_IN;
    } else if (MODE == 2) {
        a_src = g_HS + (size_t)(bm + lm) * K;
    } else {
        a_src = A + (size_t)(bm + lm) * K;
    }
    const float* b_src = W + (size_t)(bnn + lm) * K;

    float acc[16][4];
    #pragma unroll
    for (int i = 0; i < 16; i++)
        #pragma unroll
        for (int j = 0; j < 4; j++) acc[i][j] = 0.f;

    float4 ra0, ra1, rb0, rb1;
    auto ldg = [&](int k0) {
        ra0 = *(const float4*)(a_src + k0 + lk);
        ra1 = *(const float4*)(a_src + k0 + lk + 4);
        rb0 = *(const float4*)(b_src + k0 + lk);
        rb1 = *(const float4*)(b_src + k0 + lk + 4);
    };
    auto sts = [&](int buf) {
        unsigned* pa = &sA[buf][lm * TS + (lk & 8)];
        unsigned* pb = &sB[buf][lm * TS + (lk & 8)];
        pa[0] = f2tf32(ra0.x); pa[2] = f2tf32(ra0.y); pa[4] = f2tf32(ra0.z); pa[6] = f2tf32(ra0.w);
        pa[1] = f2tf32(ra1.x); pa[3] = f2tf32(ra1.y); pa[5] = f2tf32(ra1.z); pa[7] = f2tf32(ra1.w);
        pb[0] = f2tf32(rb0.x); pb[2] = f2tf32(rb0.y); pb[4] = f2tf32(rb0.z); pb[6] = f2tf32(rb0.w);
        pb[1] = f2tf32(rb1.x); pb[3] = f2tf32(rb1.y); pb[5] = f2tf32(rb1.z); pb[7] = f2tf32(rb1.w);
    };

    ldg(0); sts(0); __syncthreads();

    const int nIter = K >> 4;
    for (int it = 0; it < nIter; ++it) {
        const int cur = it & 1;
        const bool more = (it + 1 < nIter);
        if (more) ldg((it + 1) << 4);

        #pragma unroll
        for (int g = 0; g < 2; g++) {
            unsigned af[4][4], bf[4][2];
            const int aoff = g * 8 + 2 * (lane & 3);
            #pragma unroll
            for (int mt = 0; mt < 4; mt++) {
                int r = wm * 64 + mt * 16 + (lane >> 2);
                uint2 p0 = *(const uint2*)&sA[cur][r * TS + aoff];
                uint2 p1 = *(const uint2*)&sA[cur][(r + 8) * TS + aoff];
                af[mt][0] = p0.x; af[mt][2] = p0.y;
                af[mt][1] = p1.x; af[mt][3] = p1.y;
            }
            #pragma unroll
            for (int nt = 0; nt < 4; nt++) {
                int r = wn * 32 + nt * 8 + (lane >> 2);
                uint2 p = *(const uint2*)&sB[cur][r * TS + aoff];
                bf[nt][0] = p.x; bf[nt][1] = p.y;
            }
            #pragma unroll
            for (int mt = 0; mt < 4; mt++)
                #pragma unroll
                for (int nt = 0; nt < 4; nt++)
                    mma_tf32(acc[mt * 4 + nt], af[mt], bf[nt]);
        }
        if (more) sts(cur ^ 1);
        __syncthreads();
    }

    #pragma unroll
    for (int nt = 0; nt < 4; nt++) {
        int c0 = bnn + wn * 32 + nt * 8 + 2 * (lane & 3);
        float sc0 = bng[c0]     * rsqrtf(bnv[c0]     + BN_EPS);
        float sh0 = bnb[c0]     - bnm[c0]     * sc0;
        float sc1 = bng[c0 + 1] * rsqrtf(bnv[c0 + 1] + BN_EPS);
        float sh1 = bnb[c0 + 1] - bnm[c0 + 1] * sc1;
        #pragma unroll
        for (int mt = 0; mt < 4; mt++) {
            #pragma unroll
            for (int half = 0; half < 2; half++) {
                int m = bm + wm * 64 + mt * 16 + (lane >> 2) + half * 8;
                float y0 = acc[mt * 4 + nt][half * 2 + 0] * sc0 + sh0;
                float y1 = acc[mt * 4 + nt][half * 2 + 1] * sc1 + sh1;
                if (MODE == 0) {
                    int b = m / SEQ, s = m - b * SEQ;
                    #pragma unroll
                    for (int e = 0; e < 2; e++) {
                        int n = c0 + e;
                        float y = e ? y1 : y0;
                        int h = n / (KEY_DIM + D_V), c = n - h * (KEY_DIM + D_V);
                        if (c < KEY_DIM)
                            g_K[(((size_t)(b*NUM_HEADS+h))*SEQ + s)*KEY_DIM + c] = y;
                        else
                            g_V[(((size_t)(b*NUM_HEADS+h))*SEQ + s)*D_V + (c - KEY_DIM)] = y;
                    }
                } else if (MODE == 1) {
                    int b = m / SEQ_OUT, sq = m - b * SEQ_OUT;
                    int h = c0 / KEY_DIM, d = c0 - h * KEY_DIM;
                    float* p = &g_Q[(((size_t)(b*NUM_HEADS+h))*SEQ_OUT + sq)*KEY_DIM + d];
                    p[0] = y0; p[1] = y1;
                } else {
                    float* p = &out[(size_t)m * C_OUT + c0];
                    p[0] = y0; p[1] = y1;
                }
            }
        }
    }
}

// ============================================================
// Bias pre-gather: g_Bias[h][q][k] = attn_biases[h][bias_idxs[q][k]]
// ============================================================
__global__ void bias_gather(const float* __restrict__ biases,
                            const int*   __restrict__ idxs)
{
    int i = blockIdx.x * 256 + threadIdx.x;
    if (i < SEQ_OUT * SEQ) {
        int idx = idxs[i];
        #pragma unroll
        for (int h = 0; h < NUM_HEADS; h++)
            g_Bias[(size_t)h * SEQ_OUT * SEQ + i] = biases[h * N_OFF + idx];
    }
}

// ============================================================
// Flash-style tf32 tensor-core attention.
// CTA = (b, h, qb): 28 queries (padded to M=32), full 784 keys in 7
// chunks of 112. 256 threads / 8 warps. Online softmax.
// smem strides: sQ 36, sK 36, sV 136, sS 116 (all conflict-free mod 32).
// ============================================================
#define QB  28
#define KC  112
#define NCH 7

#define W_SQ 1152    // 32*36
#define W_SK 4032    // 112*36
#define W_SV 15232   // 112*136
#define W_SS 3712    // 32*116
#define W_SB 3136    // 28*112
#define ATTN_WORDS (W_SQ + W_SK + W_SV + W_SS + W_SB + 96)
#define ATTN_BYTES (ATTN_WORDS * 4)

__global__ void __launch_bounds__(256, 2)
attn_tc()
{
    extern __shared__ unsigned smw[];
    unsigned* sQ = smw;
    unsigned* sK = sQ + W_SQ;
    unsigned* sV = sK + W_SK;
    float*    sS = (float*)(sV + W_SV);
    float*    sB = sS + W_SS;
    float*    sM = sB + W_SB;
    float*    sL = sM + 32;
    float*    sF = sL + 32;

    const int t    = threadIdx.x;
    const int warp = t >> 5, lane = t & 31;
    const int cta  = blockIdx.x;
    const int qb   = cta % 7;
    const int h    = (cta / 7) % NUM_HEADS;
    const int b    = cta / (7 * NUM_HEADS);

    const float* Kp = g_K + ((size_t)(b*NUM_HEADS+h))*SEQ*KEY_DIM;
    const float* Vp = g_V + ((size_t)(b*NUM_HEADS+h))*SEQ*D_V;
    const float* Qp = g_Q + (((size_t)(b*NUM_HEADS+h))*SEQ_OUT + qb*QB)*KEY_DIM;
    const float* Bp = g_Bias + ((size_t)h*SEQ_OUT + qb*QB)*SEQ;

    // load Q (28x32, pad rows 28-31 with zeros)
    for (int i = t; i < 32*32; i += 256) {
        int r = i >> 5, d = i & 31;
        float v = (r < QB) ? Qp[r*KEY_DIM + d] : 0.f;
        sQ[r*36 + d] = f2tf32(v);
    }
    if (t < 32) { sM[t] = -1e30f; sL[t] = 0.f; sF[t] = 1.f; }

    float acc[2][2][4];
    #pragma unroll
    for (int mt = 0; mt < 2; mt++)
        #pragma unroll
        for (int nt = 0; nt < 2; nt++)
            #pragma unroll
            for (int e = 0; e < 4; e++) acc[mt][nt][e] = 0.f;

    const int lg = lane >> 2;   // 0..7
    const int lc = lane & 3;    // 0..3

    for (int ch = 0; ch < NCH; ch++) {
        const int kc = ch * KC;
        __syncthreads();

        // stage K chunk [112][32] -> sK (tf32, stride 36)
        for (int i = t*4; i < KC*KEY_DIM; i += 1024) {
            int r = i >> 5, d = i & 31;
            float4 v = *(const float4*)&Kp[(size_t)kc*KEY_DIM + i];
            unsigned* p = &sK[r*36 + d];
            p[0]=f2tf32(v.x); p[1]=f2tf32(v.y); p[2]=f2tf32(v.z); p[3]=f2tf32(v.w);
        }
        // stage V chunk [112][128] -> sV (tf32, stride 136)
        for (int i = t*4; i < KC*D_V; i += 1024) {
            int r = i >> 7, d = i & 127;
            float4 v = *(const float4*)&Vp[(size_t)kc*D_V + i];
            unsigned* p = &sV[r*136 + d];
            p[0]=f2tf32(v.x); p[1]=f2tf32(v.y); p[2]=f2tf32(v.z); p[3]=f2tf32(v.w);
        }
        // stage bias chunk [28][112]
        for (int i = t*4; i < QB*KC; i += 1024) {
            int r = i / KC, c = i - r*KC;
            float4 v = *(const float4*)&Bp[(size_t)r*SEQ + kc + c];
            *(float4*)&sB[r*KC + c] = v;
        }
        __syncthreads();

        // ---- QK^T (warp n-tiles: warps 0-5 get 2, warps 6-7 get 1) ----
        {
            int nt0 = (warp < 6) ? warp*2 : 6 + warp;   // 12,13 for warps 6,7
            int ntc = (warp < 6) ? 2 : 1;
            for (int nti = 0; nti < ntc; nti++) {
                int ntile = nt0 + nti;
                float c[2][4] = {};
                #pragma unroll
                for (int ks = 0; ks < 4; ks++) {
                    unsigned bb[2];
                    bb[0] = sK[(ntile*8 + lg)*36 + ks*8 + lc];
                    bb[1] = sK[(ntile*8 + lg)*36 + ks*8 + lc + 4];
                    #pragma unroll
                    for (int mt = 0; mt < 2; mt++) {
                        int r0 = mt*16 + lg;
                        unsigned a[4];
                        a[0] = sQ[r0*36 + ks*8 + lc];
                        a[1] = sQ[(r0+8)*36 + ks*8 + lc];
                        a[2] = sQ[r0*36 + ks*8 + lc + 4];
                        a[3] = sQ[(r0+8)*36 + ks*8 + lc + 4];
                        mma_tf32(c[mt], a, bb);
                    }
                }
                #pragma unroll
                for (int mt = 0; mt < 2; mt++) {
                    int r0 = mt*16 + lg;
                    int col = ntile*8 + 2*lc;
                    float b00 = (r0   < QB) ? sB[r0*KC + col]       : 0.f;
                    float b01 = (r0   < QB) ? sB[r0*KC + col + 1]   : 0.f;
                    float b10 = (r0+8 < QB) ? sB[(r0+8)*KC + col]   : 0.f;
                    float b11 = (r0+8 < QB) ? sB[(r0+8)*KC + col+1] : 0.f;
                    sS[r0*116 + col]       = c[mt][0]*SCALE_F + b00;
                    sS[r0*116 + col + 1]   = c[mt][1]*SCALE_F + b01;
                    sS[(r0+8)*116 + col]   = c[mt][2]*SCALE_F + b10;
                    sS[(r0+8)*116 + col+1] = c[mt][3]*SCALE_F + b11;
                }
            }
        }
        __syncthreads();

        // ---- online softmax (rows striped over warps) ----
        for (int q = warp; q < QB; q += 8) {
            float4 v;
            if (lane < 28) v = *(const float4*)&sS[q*116 + lane*4];
            else v = make_float4(-1e30f, -1e30f, -1e30f, -1e30f);
            float mx = fmaxf(fmaxf(v.x, v.y), fmaxf(v.z, v.w));
            #pragma unroll
            for (int o = 16; o; o >>= 1) mx = fmaxf(mx, __shfl_xor_sync(~0u, mx, o));
            float m_old = sM[q];
            float m_new = fmaxf(m_old, mx);
            float fac   = __expf(m_old - m_new);
            float e0 = __expf(v.x - m_new), e1 = __expf(v.y - m_new);
            float e2 = __expf(v.z - m_new), e3 = __expf(v.w - m_new);
            float s = (lane < 28) ? (e0 + e1 + e2 + e3) : 0.f;
            #pragma unroll
            for (int o = 16; o; o >>= 1) s += __shfl_xor_sync(~0u, s, o);
            if (lane < 28) {
                unsigned* p = (unsigned*)&sS[q*116 + lane*4];
                p[0]=f2tf32(e0); p[1]=f2tf32(e1); p[2]=f2tf32(e2); p[3]=f2tf32(e3);
            }
            if (lane == 0) { sM[q] = m_new; sL[q] = sL[q]*fac + s; sF[q] = fac; }
        }
        __syncthreads();

        // ---- rescale accumulators ----
        {
            float f00 = sF[lg],      f01 = sF[lg + 8];
            float f10 = sF[lg + 16], f11 = sF[lg + 24];
            #pragma unroll
            for (int nt = 0; nt < 2; nt++) {
                acc[0][nt][0] *= f00; acc[0][nt][1] *= f00;
                acc[0][nt][2] *= f01; acc[0][nt][3] *= f01;
                acc[1][nt][0] *= f10; acc[1][nt][1] *= f10;
                acc[1][nt][2] *= f11; acc[1][nt][3] *= f11;
            }
        }

        // ---- PV accumulate: each warp owns 16 output cols ----
        #pragma unroll
        for (int ks = 0; ks < 14; ks++) {
            unsigned a[2][4];
            #pragma unroll
            for (int mt = 0; mt < 2; mt++) {
                int r0 = mt*16 + lg;
                a[mt][0] = *(const unsigned*)&sS[r0*116 + ks*8 + lc];
                a[mt][1] = *(const unsigned*)&sS[(r0+8)*116 + ks*8 + lc];
                a[mt][2] = *(const unsigned*)&sS[r0*116 + ks*8 + lc + 4];
                a[mt][3] = *(const unsigned*)&sS[(r0+8)*116 + ks*8 + lc + 4];
            }
            #pragma unroll
            for (int nt = 0; nt < 2; nt++) {
                int n = warp*16 + nt*8 + lg;
                unsigned bb[2];
                bb[0] = sV[(ks*8 + lc)*136 + n];
                bb[1] = sV[(ks*8 + lc + 4)*136 + n];
                mma_tf32(acc[0][nt], a[0], bb);
                mma_tf32(acc[1][nt], a[1], bb);
            }
        }
    }

    // ---- epilogue: /l, hardswish, store ----
    #pragma unroll
    for (int mt = 0; mt < 2; mt++) {
        int rA = mt*16 + lg, rB = rA + 8;
        float invA = 1.f / sL[rA];
        float invB = 1.f / sL[rB];
        #pragma unroll
        for (int nt = 0; nt < 2; nt++) {
            int col = warp*16 + nt*8 + 2*lc;
            if (rA < QB) {
                float x0 = acc[mt][nt][0]*invA, x1 = acc[mt][nt][1]*invA;
                float h0 = x0 * fminf(fmaxf(x0+3.f,0.f),6.f) * (1.f/6.f);
                float h1 = x1 * fminf(fmaxf(x1+3.f,0.f),6.f) * (1.f/6.f);
                int q = qb*QB + rA;
                *(float2*)&g_HS[((size_t)b*SEQ_OUT + q)*OUT_PROJ + h*D_V + col] = make_float2(h0, h1);
            }
            if (rB < QB) {
                float x0 = acc[mt][nt][2]*invB, x1 = acc[mt][nt][3]*invB;
                float h0 = x0 * fminf(fmaxf(x0+3.f,0.f),6.f) * (1.f/6.f);
                float h1 = x1 * fminf(fmaxf(x1+3.f,0.f),6.f) * (1.f/6.f);
                int q = qb*QB + rB;
                *(float2*)&g_HS[((size_t)b*SEQ_OUT + q)*OUT_PROJ + h*D_V + col] = make_float2(h0, h1);
            }
        }
    }
}

// ============================================================
extern "C" void kernel_launch(void* const* d_in, const int* in_sizes, int n_in,
                              void* d_out, int out_size)
{
    const float* x      = (const float*)d_in[0];
    const float* kv_w   = (const float*)d_in[1];
    const float* kv_g   = (const float*)d_in[2];
    const float* kv_b   = (const float*)d_in[3];
    const float* kv_m   = (const float*)d_in[4];
    const float* kv_v   = (const float*)d_in[5];
    const float* q_w    = (const float*)d_in[6];
    const float* q_g    = (const float*)d_in[7];
    const float* q_b    = (const float*)d_in[8];
    const float* q_m    = (const float*)d_in[9];
    const float* q_v    = (const float*)d_in[10];
    const float* p_w    = (const float*)d_in[11];
    const float* p_g    = (const float*)d_in[12];
    const float* p_b    = (const float*)d_in[13];
    const float* p_m    = (const float*)d_in[14];
    const float* p_v    = (const float*)d_in[15];
    const float* biases = (const float*)d_in[16];
    const int*   bidx   = (const int*)d_in[17];
    float* out = (float*)d_out;

    cudaFuncSetAttribute(attn_tc, cudaFuncAttributeMaxDynamicSharedMemorySize,
                         ATTN_BYTES);

    bias_gather<<<(SEQ_OUT*SEQ + 255)/256, 256>>>(biases, bidx);

    gemm_tc<0><<<dim3(50176/128, OUT_KV/128), 256>>>(
        x, kv_w, kv_g, kv_b, kv_m, kv_v, nullptr, 50176, OUT_KV, C_IN);

    gemm_tc<1><<<dim3(12544/128, 512/128), 256>>>(
        x, q_w, q_g, q_b, q_m, q_v, nullptr, 12544, 512, C_IN);

    attn_tc<<<B_*NUM_HEADS*7, 256, ATTN_BYTES>>>();

    gemm_tc<2><<<dim3(12544/128, C_OUT/128), 256>>>(
        nullptr, p_w, p_g, p_b, p_m, p_v, out, 12544, C_OUT, OUT_PROJ);
}

// round 5
// speedup vs baseline: 3.7066x; 1.9062x over previous
#include <cuda_runtime.h>
#include <math.h>

#define B_        64
#define SEQ       784
#define SEQ_OUT   196
#define C_IN      512
#define KEY_DIM   32
#define NUM_HEADS 16
#define D_V       128
#define OUT_KV    2560
#define OUT_PROJ  2048
#define C_OUT     768
#define N_OFF     784
#define RES_OUT   14
#define SCALE_F   0.17677669529663687f
#define BN_EPS    1e-5f

// ---- scratch (static device globals; allocation-free) ----
__device__ float g_K   [(size_t)B_*NUM_HEADS*SEQ*KEY_DIM];
__device__ float g_V   [(size_t)B_*NUM_HEADS*SEQ*D_V];
__device__ float g_Q   [(size_t)B_*NUM_HEADS*SEQ_OUT*KEY_DIM];
__device__ float g_HS  [(size_t)B_*SEQ_OUT*OUT_PROJ];
__device__ float g_Bias[(size_t)NUM_HEADS*SEQ_OUT*SEQ];
__device__ float g_Xr  [(size_t)B_*SEQ*C_IN];
__device__ float g_Wkv [(size_t)OUT_KV*C_IN];
__device__ float g_Wq  [(size_t)KEY_DIM*NUM_HEADS*C_IN];
__device__ float g_Wp  [(size_t)C_OUT*OUT_PROJ];

__device__ __forceinline__ unsigned f2tf32(float f) {
    unsigned r;
    asm("cvt.rna.tf32.f32 %0, %1;" : "=r"(r) : "f"(f));
    return r;
}
__device__ __forceinline__ float rtf32(float f) { return __uint_as_float(f2tf32(f)); }

__device__ __forceinline__ unsigned sm_u32(const void* p) {
    return (unsigned)__cvta_generic_to_shared(p);
}
#define CPA16(dst, src) asm volatile("cp.async.cg.shared.global [%0], [%1], 16;" :: "r"(dst), "l"(src))
#define CPCOMMIT()      asm volatile("cp.async.commit_group;")
#define CPWAIT(n)       asm volatile("cp.async.wait_group %0;" :: "n"(n))

__device__ __forceinline__ void mma_tf32(float* c, const unsigned* a, const unsigned* b) {
    asm volatile(
        "mma.sync.aligned.m16n8k8.row.col.f32.tf32.tf32.f32 "
        "{%0,%1,%2,%3}, {%4,%5,%6,%7}, {%8,%9}, {%0,%1,%2,%3};"
        : "+f"(c[0]), "+f"(c[1]), "+f"(c[2]), "+f"(c[3])
        : "r"(a[0]), "r"(a[1]), "r"(a[2]), "r"(a[3]), "r"(b[0]), "r"(b[1]));
}

// ============================================================
// tf32 rounding copy (vectorized)
// ============================================================
__global__ void round_copy(const float* __restrict__ src, float* __restrict__ dst, int n4)
{
    int i = blockIdx.x * 256 + threadIdx.x;
    if (i < n4) {
        float4 v = ((const float4*)src)[i];
        v.x = rtf32(v.x); v.y = rtf32(v.y); v.z = rtf32(v.z); v.w = rtf32(v.w);
        ((float4*)dst)[i] = v;
    }
}

// ============================================================
// Bias pre-gather: g_Bias[h][q][k] = attn_biases[h][bias_idxs[q][k]]
// ============================================================
__global__ void bias_gather(const float* __restrict__ biases,
                            const int*   __restrict__ idxs)
{
    int i = blockIdx.x * 256 + threadIdx.x;
    if (i < SEQ_OUT * SEQ) {
        int idx = idxs[i];
        #pragma unroll
        for (int h = 0; h < NUM_HEADS; h++)
            g_Bias[(size_t)h * SEQ_OUT * SEQ + i] = biases[h * N_OFF + idx];
    }
}

// ============================================================
// TF32 GEMM, 4-stage cp.async pipeline.
// C[M,N] = A[M,K] @ W[N,K]^T + BN.  Inputs pre-rounded to tf32.
// CTA 128x128xBK16, 256 threads (8 warps 2x4), warp tile 64x32.
// smem rows stride 20 words (conflict-free LDS.32 frag loads).
// MODE 0: A=g_Xr -> split g_K/g_V (tf32-rounded)
// MODE 1: A=g_Xr gathered rows -> g_Q (tf32-rounded)
// MODE 2: A=g_HS (device global, A arg ignored) -> d_out (full f32)
// ============================================================
#define GST  20
#define NSTG 4
#define GEMM_SMEM_BYTES (2*NSTG*128*GST*4)   // 81920

template<int MODE>
__global__ void __launch_bounds__(256, 2)
gemm_tc(const float* __restrict__ A, const float* __restrict__ W,
        const float* __restrict__ bng, const float* __restrict__ bnb,
        const float* __restrict__ bnm, const float* __restrict__ bnv,
        float* __restrict__ out, int M, int N, int K)
{
    extern __shared__ float smemf[];
    float* SA = smemf;
    float* SB = smemf + NSTG*128*GST;

    const int t    = threadIdx.x;
    const int warp = t >> 5, lane = t & 31;
    const int wm   = warp >> 2, wn = warp & 3;
    const int bm   = blockIdx.x * 128;
    const int bnn  = blockIdx.y * 128;
    const int lg   = lane >> 2, lc = lane & 3;

    // copy assignment: thread owns 16B chunks t and t+256 of each 128x16 tile
    const int r0 = t >> 2,        d0 = (t & 3) * 4;
    const int r1 = (t + 256) >> 2, d1 = ((t + 256) & 3) * 4;

    auto a_row = [&](int r) -> const float* {
        if (MODE == 1) {
            int row = bm + r;
            int b = row / SEQ_OUT, sq = row - b * SEQ_OUT;
            int rr = sq / RES_OUT, cc = sq - rr * RES_OUT;
            return A + ((size_t)b * SEQ + (2*rr*28 + 2*cc)) * C_IN;
        }
        if (MODE == 2) {
            return g_HS + (size_t)(bm + r) * K;   // FIX: was nullptr-based in R4
        }
        return A + (size_t)(bm + r) * K;
    };
    const float* aP0 = a_row(r0);
    const float* aP1 = a_row(r1);
    const float* bP0 = W + (size_t)(bnn + r0) * K;
    const float* bP1 = W + (size_t)(bnn + r1) * K;

    const unsigned sbase = sm_u32(smemf);
    const unsigned aA0 = sbase + (r0*GST + d0)*4;
    const unsigned aA1 = sbase + (r1*GST + d1)*4;
    const unsigned bA0 = sbase + (NSTG*128*GST + r0*GST + d0)*4;
    const unsigned bA1 = sbase + (NSTG*128*GST + r1*GST + d1)*4;

    auto issue = [&](int s, int k0) {
        unsigned so = s * 128*GST*4;
        CPA16(aA0 + so, aP0 + k0 + d0);
        CPA16(aA1 + so, aP1 + k0 + d1);
        CPA16(bA0 + so, bP0 + k0 + d0);
        CPA16(bA1 + so, bP1 + k0 + d1);
    };

    float acc[16][4];
    #pragma unroll
    for (int i = 0; i < 16; i++)
        #pragma unroll
        for (int j = 0; j < 4; j++) acc[i][j] = 0.f;

    const int nIter = K >> 4;
    #pragma unroll
    for (int s = 0; s < 3; s++) { issue(s, s << 4); CPCOMMIT(); }

    for (int it = 0; it < nIter; ++it) {
        CPWAIT(2);
        __syncthreads();
        const float* pA = SA + (it & 3) * 128*GST;
        const float* pB = SB + (it & 3) * 128*GST;

        #pragma unroll
        for (int g = 0; g < 2; g++) {
            const int ko = g*8 + lc;
            unsigned af[4][4], bf[4][2];
            #pragma unroll
            for (int mt = 0; mt < 4; mt++) {
                int r = wm*64 + mt*16 + lg;
                af[mt][0] = __float_as_uint(pA[r*GST + ko]);
                af[mt][1] = __float_as_uint(pA[(r+8)*GST + ko]);
                af[mt][2] = __float_as_uint(pA[r*GST + ko + 4]);
                af[mt][3] = __float_as_uint(pA[(r+8)*GST + ko + 4]);
            }
            #pragma unroll
            for (int nt = 0; nt < 4; nt++) {
                int rn = wn*32 + nt*8 + lg;
                bf[nt][0] = __float_as_uint(pB[rn*GST + ko]);
                bf[nt][1] = __float_as_uint(pB[rn*GST + ko + 4]);
            }
            #pragma unroll
            for (int mt = 0; mt < 4; mt++)
                #pragma unroll
                for (int nt = 0; nt < 4; nt++)
                    mma_tf32(acc[mt*4 + nt], af[mt], bf[nt]);
        }

        if (it + 3 < nIter) issue((it + 3) & 3, (it + 3) << 4);
        CPCOMMIT();
    }

    // ---- BN epilogue + scatter ----
    #pragma unroll
    for (int nt = 0; nt < 4; nt++) {
        int c0 = bnn + wn*32 + nt*8 + 2*lc;
        float sc0 = bng[c0]     * rsqrtf(bnv[c0]     + BN_EPS);
        float sh0 = bnb[c0]     - bnm[c0]     * sc0;
        float sc1 = bng[c0 + 1] * rsqrtf(bnv[c0 + 1] + BN_EPS);
        float sh1 = bnb[c0 + 1] - bnm[c0 + 1] * sc1;
        #pragma unroll
        for (int mt = 0; mt < 4; mt++) {
            #pragma unroll
            for (int half = 0; half < 2; half++) {
                int m = bm + wm*64 + mt*16 + lg + half*8;
                float y0 = acc[mt*4 + nt][half*2 + 0] * sc0 + sh0;
                float y1 = acc[mt*4 + nt][half*2 + 1] * sc1 + sh1;
                if (MODE == 0) {
                    int b = m / SEQ, s = m - b * SEQ;
                    #pragma unroll
                    for (int e = 0; e < 2; e++) {
                        int n = c0 + e;
                        float y = rtf32(e ? y1 : y0);
                        int h = n / (KEY_DIM + D_V), c = n - h * (KEY_DIM + D_V);
                        if (c < KEY_DIM)
                            g_K[(((size_t)(b*NUM_HEADS+h))*SEQ + s)*KEY_DIM + c] = y;
                        else
                            g_V[(((size_t)(b*NUM_HEADS+h))*SEQ + s)*D_V + (c - KEY_DIM)] = y;
                    }
                } else if (MODE == 1) {
                    int b = m / SEQ_OUT, sq = m - b * SEQ_OUT;
                    int h = c0 / KEY_DIM, d = c0 - h * KEY_DIM;
                    float* p = &g_Q[(((size_t)(b*NUM_HEADS+h))*SEQ_OUT + sq)*KEY_DIM + d];
                    p[0] = rtf32(y0); p[1] = rtf32(y1);
                } else {
                    float* p = &out[(size_t)m * C_OUT + c0];
                    p[0] = y0; p[1] = y1;
                }
            }
        }
    }
}

// ============================================================
// Flash-style tf32 attention with cp.async staging.
// K (grp0) + bias (grp1) waited before QK^T; V (grp2) streams
// during QK^T + softmax, waited before PV.
// ============================================================
#define QB  28
#define KC  112
#define NCH 7

#define W_SQ 1152
#define W_SK 4032
#define W_SV 15232
#define W_SS 3712
#define W_SB 3136
#define ATTN_WORDS (W_SQ + W_SK + W_SV + W_SS + W_SB + 96)
#define ATTN_BYTES (ATTN_WORDS * 4)

__global__ void __launch_bounds__(256, 2)
attn_tc()
{
    extern __shared__ unsigned smw[];
    unsigned* sQ = smw;
    unsigned* sK = sQ + W_SQ;
    unsigned* sV = sK + W_SK;
    float*    sS = (float*)(sV + W_SV);
    float*    sB = sS + W_SS;
    float*    sM = sB + W_SB;
    float*    sL = sM + 32;
    float*    sF = sL + 32;

    const int t    = threadIdx.x;
    const int warp = t >> 5, lane = t & 31;
    const int cta  = blockIdx.x;
    const int qb   = cta % 7;
    const int h    = (cta / 7) % NUM_HEADS;
    const int b    = cta / (7 * NUM_HEADS);

    const float* Kp = g_K + ((size_t)(b*NUM_HEADS+h))*SEQ*KEY_DIM;
    const float* Vp = g_V + ((size_t)(b*NUM_HEADS+h))*SEQ*D_V;
    const float* Qp = g_Q + (((size_t)(b*NUM_HEADS+h))*SEQ_OUT + qb*QB)*KEY_DIM;
    const float* Bp = g_Bias + ((size_t)h*SEQ_OUT + qb*QB)*SEQ;

    const unsigned sKb = sm_u32(sK);
    const unsigned sVb = sm_u32(sV);
    const unsigned sBb = sm_u32(sB);

    for (int i = t; i < 32*32; i += 256) {
        int r = i >> 5, d = i & 31;
        float v = (r < QB) ? Qp[r*KEY_DIM + d] : 0.f;
        sQ[r*36 + d] = __float_as_uint(v);
    }
    if (t < 32) { sM[t] = -1e30f; sL[t] = 0.f; sF[t] = 1.f; }

    float acc[2][2][4];
    #pragma unroll
    for (int mt = 0; mt < 2; mt++)
        #pragma unroll
        for (int nt = 0; nt < 2; nt++)
            #pragma unroll
            for (int e = 0; e < 4; e++) acc[mt][nt][e] = 0.f;

    const int lg = lane >> 2;
    const int lc = lane & 3;

    for (int ch = 0; ch < NCH; ch++) {
        const int kc = ch * KC;
        __syncthreads();   // prev chunk fully consumed (sS/sV/sB reusable)

        // K chunk [112][32] -> stride 36 (grp 0)
        for (int i = t*4; i < KC*KEY_DIM; i += 1024) {
            int r = i >> 5, d = i & 31;
            CPA16(sKb + (r*36 + d)*4, &Kp[(size_t)kc*KEY_DIM + i]);
        }
        CPCOMMIT();
        // bias chunk [28][112] (grp 1)
        for (int i = t*4; i < QB*KC; i += 1024) {
            int r = i / KC, c = i - r*KC;
            CPA16(sBb + (r*KC + c)*4, &Bp[(size_t)r*SEQ + kc + c]);
        }
        CPCOMMIT();
        // V chunk [112][128] -> stride 136 (grp 2)
        for (int i = t*4; i < KC*D_V; i += 1024) {
            int r = i >> 7, d = i & 127;
            CPA16(sVb + (r*136 + d)*4, &Vp[(size_t)kc*D_V + i]);
        }
        CPCOMMIT();

        CPWAIT(1);          // K + bias ready; V streaming
        __syncthreads();

        // ---- QK^T ----
        {
            int nt0 = (warp < 6) ? warp*2 : 6 + warp;
            int ntc = (warp < 6) ? 2 : 1;
            for (int nti = 0; nti < ntc; nti++) {
                int ntile = nt0 + nti;
                float c[2][4] = {};
                #pragma unroll
                for (int ks = 0; ks < 4; ks++) {
                    unsigned bb[2];
                    bb[0] = sK[(ntile*8 + lg)*36 + ks*8 + lc];
                    bb[1] = sK[(ntile*8 + lg)*36 + ks*8 + lc + 4];
                    #pragma unroll
                    for (int mt = 0; mt < 2; mt++) {
                        int r0 = mt*16 + lg;
                        unsigned a[4];
                        a[0] = sQ[r0*36 + ks*8 + lc];
                        a[1] = sQ[(r0+8)*36 + ks*8 + lc];
                        a[2] = sQ[r0*36 + ks*8 + lc + 4];
                        a[3] = sQ[(r0+8)*36 + ks*8 + lc + 4];
                        mma_tf32(c[mt], a, bb);
                    }
                }
                #pragma unroll
                for (int mt = 0; mt < 2; mt++) {
                    int r0 = mt*16 + lg;
                    int col = ntile*8 + 2*lc;
                    float b00 = (r0   < QB) ? sB[r0*KC + col]       : 0.f;
                    float b01 = (r0   < QB) ? sB[r0*KC + col + 1]   : 0.f;
                    float b10 = (r0+8 < QB) ? sB[(r0+8)*KC + col]   : 0.f;
                    float b11 = (r0+8 < QB) ? sB[(r0+8)*KC + col+1] : 0.f;
                    sS[r0*116 + col]       = c[mt][0]*SCALE_F + b00;
                    sS[r0*116 + col + 1]   = c[mt][1]*SCALE_F + b01;
                    sS[(r0+8)*116 + col]   = c[mt][2]*SCALE_F + b10;
                    sS[(r0+8)*116 + col+1] = c[mt][3]*SCALE_F + b11;
                }
            }
        }
        __syncthreads();

        // ---- online softmax ----
        for (int q = warp; q < QB; q += 8) {
            float4 v;
            if (lane < 28) v = *(const float4*)&sS[q*116 + lane*4];
            else v = make_float4(-1e30f, -1e30f, -1e30f, -1e30f);
            float mx = fmaxf(fmaxf(v.x, v.y), fmaxf(v.z, v.w));
            #pragma unroll
            for (int o = 16; o; o >>= 1) mx = fmaxf(mx, __shfl_xor_sync(~0u, mx, o));
            float m_old = sM[q];
            float m_new = fmaxf(m_old, mx);
            float fac   = __expf(m_old - m_new);
            float e0 = __expf(v.x - m_new), e1 = __expf(v.y - m_new);
            float e2 = __expf(v.z - m_new), e3 = __expf(v.w - m_new);
            float s = (lane < 28) ? (e0 + e1 + e2 + e3) : 0.f;
            #pragma unroll
            for (int o = 16; o; o >>= 1) s += __shfl_xor_sync(~0u, s, o);
            if (lane < 28) {
                unsigned* p = (unsigned*)&sS[q*116 + lane*4];
                p[0]=f2tf32(e0); p[1]=f2tf32(e1); p[2]=f2tf32(e2); p[3]=f2tf32(e3);
            }
            if (lane == 0) { sM[q] = m_new; sL[q] = sL[q]*fac + s; sF[q] = fac; }
        }
        CPWAIT(0);          // V ready
        __syncthreads();

        // ---- rescale accumulators ----
        {
            float f00 = sF[lg],      f01 = sF[lg + 8];
            float f10 = sF[lg + 16], f11 = sF[lg + 24];
            #pragma unroll
            for (int nt = 0; nt < 2; nt++) {
                acc[0][nt][0] *= f00; acc[0][nt][1] *= f00;
                acc[0][nt][2] *= f01; acc[0][nt][3] *= f01;
                acc[1][nt][0] *= f10; acc[1][nt][1] *= f10;
                acc[1][nt][2] *= f11; acc[1][nt][3] *= f11;
            }
        }

        // ---- PV accumulate ----
        #pragma unroll
        for (int ks = 0; ks < 14; ks++) {
            unsigned a[2][4];
            #pragma unroll
            for (int mt = 0; mt < 2; mt++) {
                int r0 = mt*16 + lg;
                a[mt][0] = *(const unsigned*)&sS[r0*116 + ks*8 + lc];
                a[mt][1] = *(const unsigned*)&sS[(r0+8)*116 + ks*8 + lc];
                a[mt][2] = *(const unsigned*)&sS[r0*116 + ks*8 + lc + 4];
                a[mt][3] = *(const unsigned*)&sS[(r0+8)*116 + ks*8 + lc + 4];
            }
            #pragma unroll
            for (int nt = 0; nt < 2; nt++) {
                int n = warp*16 + nt*8 + lg;
                unsigned bb[2];
                bb[0] = sV[(ks*8 + lc)*136 + n];
                bb[1] = sV[(ks*8 + lc + 4)*136 + n];
                mma_tf32(acc[0][nt], a[0], bb);
                mma_tf32(acc[1][nt], a[1], bb);
            }
        }
    }

    // ---- epilogue: /l, hardswish, tf32-round, store ----
    #pragma unroll
    for (int mt = 0; mt < 2; mt++) {
        int rA = mt*16 + lg, rB = rA + 8;
        float invA = 1.f / sL[rA];
        float invB = 1.f / sL[rB];
        #pragma unroll
        for (int nt = 0; nt < 2; nt++) {
            int col = warp*16 + nt*8 + 2*lc;
            if (rA < QB) {
                float x0 = acc[mt][nt][0]*invA, x1 = acc[mt][nt][1]*invA;
                float h0 = rtf32(x0 * fminf(fmaxf(x0+3.f,0.f),6.f) * (1.f/6.f));
                float h1 = rtf32(x1 * fminf(fmaxf(x1+3.f,0.f),6.f) * (1.f/6.f));
                int q = qb*QB + rA;
                *(float2*)&g_HS[((size_t)b*SEQ_OUT + q)*OUT_PROJ + h*D_V + col] = make_float2(h0, h1);
            }
            if (rB < QB) {
                float x0 = acc[mt][nt][2]*invB, x1 = acc[mt][nt][3]*invB;
                float h0 = rtf32(x0 * fminf(fmaxf(x0+3.f,0.f),6.f) * (1.f/6.f));
                float h1 = rtf32(x1 * fminf(fmaxf(x1+3.f,0.f),6.f) * (1.f/6.f));
                int q = qb*QB + rB;
                *(float2*)&g_HS[((size_t)b*SEQ_OUT + q)*OUT_PROJ + h*D_V + col] = make_float2(h0, h1);
            }
        }
    }
}

// ============================================================
extern "C" void kernel_launch(void* const* d_in, const int* in_sizes, int n_in,
                              void* d_out, int out_size)
{
    const float* x      = (const float*)d_in[0];
    const float* kv_w   = (const float*)d_in[1];
    const float* kv_g   = (const float*)d_in[2];
    const float* kv_b   = (const float*)d_in[3];
    const float* kv_m   = (const float*)d_in[4];
    const float* kv_v   = (const float*)d_in[5];
    const float* q_w    = (const float*)d_in[6];
    const float* q_g    = (const float*)d_in[7];
    const float* q_b    = (const float*)d_in[8];
    const float* q_m    = (const float*)d_in[9];
    const float* q_v    = (const float*)d_in[10];
    const float* p_w    = (const float*)d_in[11];
    const float* p_g    = (const float*)d_in[12];
    const float* p_b    = (const float*)d_in[13];
    const float* p_m    = (const float*)d_in[14];
    const float* p_v    = (const float*)d_in[15];
    const float* biases = (const float*)d_in[16];
    const int*   bidx   = (const int*)d_in[17];
    float* out = (float*)d_out;

    cudaFuncSetAttribute(attn_tc, cudaFuncAttributeMaxDynamicSharedMemorySize, ATTN_BYTES);
    cudaFuncSetAttribute(gemm_tc<0>, cudaFuncAttributeMaxDynamicSharedMemorySize, GEMM_SMEM_BYTES);
    cudaFuncSetAttribute(gemm_tc<1>, cudaFuncAttributeMaxDynamicSharedMemorySize, GEMM_SMEM_BYTES);
    cudaFuncSetAttribute(gemm_tc<2>, cudaFuncAttributeMaxDynamicSharedMemorySize, GEMM_SMEM_BYTES);

    float *d_xr, *d_wkv, *d_wq, *d_wp;
    cudaGetSymbolAddress((void**)&d_xr,  g_Xr);
    cudaGetSymbolAddress((void**)&d_wkv, g_Wkv);
    cudaGetSymbolAddress((void**)&d_wq,  g_Wq);
    cudaGetSymbolAddress((void**)&d_wp,  g_Wp);

    round_copy<<<(B_*SEQ*C_IN/4 + 255)/256, 256>>>(x, d_xr, B_*SEQ*C_IN/4);
    round_copy<<<(OUT_KV*C_IN/4 + 255)/256, 256>>>(kv_w, d_wkv, OUT_KV*C_IN/4);
    round_copy<<<(KEY_DIM*NUM_HEADS*C_IN/4 + 255)/256, 256>>>(q_w, d_wq, KEY_DIM*NUM_HEADS*C_IN/4);
    round_copy<<<(C_OUT*OUT_PROJ/4 + 255)/256, 256>>>(p_w, d_wp, C_OUT*OUT_PROJ/4);
    bias_gather<<<(SEQ_OUT*SEQ + 255)/256, 256>>>(biases, bidx);

    gemm_tc<0><<<dim3(50176/128, OUT_KV/128), 256, GEMM_SMEM_BYTES>>>(
        d_xr, d_wkv, kv_g, kv_b, kv_m, kv_v, nullptr, 50176, OUT_KV, C_IN);

    gemm_tc<1><<<dim3(12544/128, 512/128), 256, GEMM_SMEM_BYTES>>>(
        d_xr, d_wq, q_g, q_b, q_m, q_v, nullptr, 12544, 512, C_IN);

    attn_tc<<<B_*NUM_HEADS*7, 256, ATTN_BYTES>>>();

    gemm_tc<2><<<dim3(12544/128, C_OUT/128), 256, GEMM_SMEM_BYTES>>>(
        nullptr, d_wp, p_g, p_b, p_m, p_v, out, 12544, C_OUT, OUT_PROJ);
}